// round 1
// baseline (speedup 1.0000x reference)
#include <cuda_runtime.h>
#include <math.h>

// Problem constants
#define B_  32
#define DM  512
#define S_  64
#define L_  4096

// Scratch (device globals - no allocation allowed)
__device__ float g_bcdt_raw[(size_t)B_ * 3 * S_ * L_];   // [B,192,L] pre-conv
__device__ float g_bcdt    [(size_t)B_ * 3 * S_ * L_];   // [B,192,L] post-conv; ch 0..63=Bm, 64..127=Cm, 128..191=dt->AB
__device__ float g_h       [(size_t)B_ * DM * S_];       // [B,512,64]
__device__ float g_hz      [(size_t)B_ * 2 * DM * S_];   // [B,1024,64]
__device__ float g_hg      [(size_t)B_ * DM * S_];       // [B,512,64]

// ---------------------------------------------------------------------------
// Generic NN GEMM: C[M,N] = A[M,K] @ B[K,N] (+bias[M]), all row-major.
// Tile 64x64, K-chunk 16, 256 threads, 4x4 microtile.
// Requires: M%64==0 (via grid), N%64==0, K%16==0, 16B-aligned rows.
// ---------------------------------------------------------------------------
template <bool HAS_BIAS>
__global__ void __launch_bounds__(256) gemm_nn_kernel(
    const float* __restrict__ A, long long sA,
    const float* __restrict__ B, long long sB,
    float* __restrict__ C, long long sC,
    const float* __restrict__ bias,
    int N, int K)
{
    __shared__ float As[16][65];   // [k][m], padded
    __shared__ float Bs[16][64];   // [k][n]

    const int bz = blockIdx.z;
    A += (size_t)bz * sA;
    B += (size_t)bz * sB;
    C += (size_t)bz * sC;

    const int m0 = blockIdx.y * 64;
    const int n0 = blockIdx.x * 64;
    const int t  = threadIdx.x;
    const int tx = t & 15, ty = t >> 4;

    const int lm  = t >> 2;          // 0..63
    const int lk4 = (t & 3) << 2;    // 0,4,8,12
    const int bk  = t >> 4;          // 0..15
    const int bn4 = (t & 15) << 2;   // 0..60

    float acc[4][4] = {};

    for (int k0 = 0; k0 < K; k0 += 16) {
        float4 av = *(const float4*)(A + (size_t)(m0 + lm) * K + k0 + lk4);
        As[lk4 + 0][lm] = av.x;
        As[lk4 + 1][lm] = av.y;
        As[lk4 + 2][lm] = av.z;
        As[lk4 + 3][lm] = av.w;
        *(float4*)&Bs[bk][bn4] =
            *(const float4*)(B + (size_t)(k0 + bk) * N + n0 + bn4);
        __syncthreads();

#pragma unroll
        for (int kk = 0; kk < 16; kk++) {
            float a0 = As[kk][ty * 4 + 0];
            float a1 = As[kk][ty * 4 + 1];
            float a2 = As[kk][ty * 4 + 2];
            float a3 = As[kk][ty * 4 + 3];
            float4 bv = *(const float4*)&Bs[kk][tx * 4];
            acc[0][0] += a0 * bv.x; acc[0][1] += a0 * bv.y; acc[0][2] += a0 * bv.z; acc[0][3] += a0 * bv.w;
            acc[1][0] += a1 * bv.x; acc[1][1] += a1 * bv.y; acc[1][2] += a1 * bv.z; acc[1][3] += a1 * bv.w;
            acc[2][0] += a2 * bv.x; acc[2][1] += a2 * bv.y; acc[2][2] += a2 * bv.z; acc[2][3] += a2 * bv.w;
            acc[3][0] += a3 * bv.x; acc[3][1] += a3 * bv.y; acc[3][2] += a3 * bv.z; acc[3][3] += a3 * bv.w;
        }
        __syncthreads();
    }

#pragma unroll
    for (int i = 0; i < 4; i++) {
        int row = m0 + ty * 4 + i;
        float bi = HAS_BIAS ? bias[row] : 0.0f;
        float4 o;
        o.x = acc[i][0] + bi;
        o.y = acc[i][1] + bi;
        o.z = acc[i][2] + bi;
        o.w = acc[i][3] + bi;
        *(float4*)(C + (size_t)row * N + n0 + tx * 4) = o;
    }
}

// ---------------------------------------------------------------------------
// NT GEMM: C[M,N] = A[M,K] @ B[N,K]^T, A and B row-major (both K-contiguous).
// Same tiling as above.
// ---------------------------------------------------------------------------
__global__ void __launch_bounds__(256) gemm_nt_kernel(
    const float* __restrict__ A, long long sA,
    const float* __restrict__ B, long long sB,
    float* __restrict__ C, long long sC,
    int N, int K)
{
    __shared__ float As[16][65];
    __shared__ float Bs[16][65];

    const int bz = blockIdx.z;
    A += (size_t)bz * sA;
    B += (size_t)bz * sB;
    C += (size_t)bz * sC;

    const int m0 = blockIdx.y * 64;
    const int n0 = blockIdx.x * 64;
    const int t  = threadIdx.x;
    const int tx = t & 15, ty = t >> 4;

    const int lr  = t >> 2;          // 0..63 (row in A or B)
    const int lk4 = (t & 3) << 2;    // 0,4,8,12

    float acc[4][4] = {};

    for (int k0 = 0; k0 < K; k0 += 16) {
        float4 av = *(const float4*)(A + (size_t)(m0 + lr) * K + k0 + lk4);
        As[lk4 + 0][lr] = av.x;
        As[lk4 + 1][lr] = av.y;
        As[lk4 + 2][lr] = av.z;
        As[lk4 + 3][lr] = av.w;
        float4 bv = *(const float4*)(B + (size_t)(n0 + lr) * K + k0 + lk4);
        Bs[lk4 + 0][lr] = bv.x;
        Bs[lk4 + 1][lr] = bv.y;
        Bs[lk4 + 2][lr] = bv.z;
        Bs[lk4 + 3][lr] = bv.w;
        __syncthreads();

#pragma unroll
        for (int kk = 0; kk < 16; kk++) {
            float a0 = As[kk][ty * 4 + 0];
            float a1 = As[kk][ty * 4 + 1];
            float a2 = As[kk][ty * 4 + 2];
            float a3 = As[kk][ty * 4 + 3];
            float b0 = Bs[kk][tx * 4 + 0];
            float b1 = Bs[kk][tx * 4 + 1];
            float b2 = Bs[kk][tx * 4 + 2];
            float b3 = Bs[kk][tx * 4 + 3];
            acc[0][0] += a0 * b0; acc[0][1] += a0 * b1; acc[0][2] += a0 * b2; acc[0][3] += a0 * b3;
            acc[1][0] += a1 * b0; acc[1][1] += a1 * b1; acc[1][2] += a1 * b2; acc[1][3] += a1 * b3;
            acc[2][0] += a2 * b0; acc[2][1] += a2 * b1; acc[2][2] += a2 * b2; acc[2][3] += a2 * b3;
            acc[3][0] += a3 * b0; acc[3][1] += a3 * b1; acc[3][2] += a3 * b2; acc[3][3] += a3 * b3;
        }
        __syncthreads();
    }

#pragma unroll
    for (int i = 0; i < 4; i++) {
        int row = m0 + ty * 4 + i;
        float4 o;
        o.x = acc[i][0];
        o.y = acc[i][1];
        o.z = acc[i][2];
        o.w = acc[i][3];
        *(float4*)(C + (size_t)row * N + n0 + tx * 4) = o;
    }
}

// ---------------------------------------------------------------------------
// Depthwise 3x3 conv, pad 1, on [B,192,64,64]. One block per (ch, b) plane.
// ---------------------------------------------------------------------------
__global__ void __launch_bounds__(256) dwconv_kernel(
    const float* __restrict__ in, float* __restrict__ out,
    const float* __restrict__ w, const float* __restrict__ bias)
{
    __shared__ float sp[64 * 64];
    __shared__ float wv[9];

    const int ch = blockIdx.x;   // 0..191
    const int b  = blockIdx.y;   // 0..31
    const size_t base = ((size_t)b * 192 + ch) * 4096;
    const float* ip = in + base;
    float* op = out + base;

    for (int i = threadIdx.x; i < 4096; i += 256) sp[i] = ip[i];
    if (threadIdx.x < 9) wv[threadIdx.x] = w[ch * 9 + threadIdx.x];
    __syncthreads();

    const float bv = bias[ch];
    for (int idx = threadIdx.x; idx < 4096; idx += 256) {
        const int i = idx >> 6, j = idx & 63;
        float s = bv;
#pragma unroll
        for (int di = 0; di < 3; di++) {
            const int ii = i + di - 1;
            if (ii < 0 || ii > 63) continue;
#pragma unroll
            for (int dj = 0; dj < 3; dj++) {
                const int jj = j + dj - 1;
                if (jj < 0 || jj > 63) continue;
                s += wv[di * 3 + dj] * sp[(ii << 6) + jj];
            }
        }
        op[idx] = s;
    }
}

// ---------------------------------------------------------------------------
// Softmax over L of dt (A[s] is constant along the softmax axis -> cancels),
// then AB = softmax(dt) * Bm, written in place over the dt channel block.
// One block per (s, b) row of length 4096.
// ---------------------------------------------------------------------------
__global__ void __launch_bounds__(256) softmax_ab_kernel(float* __restrict__ bcdt)
{
    const int s = blockIdx.x;   // 0..63
    const int b = blockIdx.y;   // 0..31
    float* dt       = bcdt + ((size_t)b * 192 + 128 + s) * 4096;
    const float* Bm = bcdt + ((size_t)b * 192 + s) * 4096;

    __shared__ float red[256];
    const int tid = threadIdx.x;

    float mx = -3.4e38f;
    for (int i = tid; i < 4096; i += 256) mx = fmaxf(mx, dt[i]);
    red[tid] = mx;
    __syncthreads();
    for (int off = 128; off > 0; off >>= 1) {
        if (tid < off) red[tid] = fmaxf(red[tid], red[tid + off]);
        __syncthreads();
    }
    mx = red[0];
    __syncthreads();

    float sum = 0.0f;
    for (int i = tid; i < 4096; i += 256) sum += expf(dt[i] - mx);
    red[tid] = sum;
    __syncthreads();
    for (int off = 128; off > 0; off >>= 1) {
        if (tid < off) red[tid] += red[tid + off];
        __syncthreads();
    }
    const float inv = 1.0f / red[0];

    for (int i = tid; i < 4096; i += 256)
        dt[i] = expf(dt[i] - mx) * inv * Bm[i];
}

// ---------------------------------------------------------------------------
// Gating: hg[b,o,s] = h1 * silu(z) + h1 * Dskip,  h1=hz[b,o,s], z=hz[b,512+o,s]
// ---------------------------------------------------------------------------
__global__ void __launch_bounds__(256) gate_kernel(
    const float* __restrict__ hz, float* __restrict__ hg,
    const float* __restrict__ Dskip)
{
    const size_t total = (size_t)B_ * DM * S_;
    const size_t i = (size_t)blockIdx.x * 256 + threadIdx.x;
    if (i >= total) return;
    const int s = (int)(i & 63);
    const size_t rest = i >> 6;
    const int o = (int)(rest & 511);
    const int b = (int)(rest >> 9);
    const float* base = hz + (size_t)b * 2 * DM * S_;
    const float h1 = base[(size_t)o * 64 + s];
    const float z  = base[(size_t)(DM + o) * 64 + s];
    const float sig = 1.0f / (1.0f + expf(-z));
    hg[i] = h1 * (z * sig) + h1 * Dskip[0];
}

// ---------------------------------------------------------------------------
// Host launch
// ---------------------------------------------------------------------------
extern "C" void kernel_launch(void* const* d_in, const int* in_sizes, int n_in,
                              void* d_out, int out_size)
{
    (void)in_sizes; (void)n_in; (void)out_size;

    const float* x      = (const float*)d_in[0];   // [32,512,4096]
    const float* w_bcdt = (const float*)d_in[1];   // [192,512]
    const float* b_bcdt = (const float*)d_in[2];   // [192]
    const float* w_dw   = (const float*)d_in[3];   // [192,1,3,3]
    const float* b_dw   = (const float*)d_in[4];   // [192]
    const float* w_hz   = (const float*)d_in[5];   // [1024,512]
    const float* b_hz   = (const float*)d_in[6];   // [1024]
    const float* w_out  = (const float*)d_in[7];   // [512,512]
    const float* b_out  = (const float*)d_in[8];   // [512]
    // d_in[9] = A (cancels inside softmax over L), d_in[11]/[12] = H,W (fixed 64)
    const float* Dskip  = (const float*)d_in[10];  // [1]

    float* out = (float*)d_out;
    float* y  = out;                               // [32,512,4096]
    float* ho = out + (size_t)B_ * DM * L_;        // [32,512,64]

    float *bcdt_raw, *bcdt, *h, *hz, *hg;
    cudaGetSymbolAddress((void**)&bcdt_raw, g_bcdt_raw);
    cudaGetSymbolAddress((void**)&bcdt,     g_bcdt);
    cudaGetSymbolAddress((void**)&h,        g_h);
    cudaGetSymbolAddress((void**)&hz,       g_hz);
    cudaGetSymbolAddress((void**)&hg,       g_hg);

    const dim3 blk(256);
    const long long sX    = (long long)DM * L_;       // x batch stride
    const long long sBCDT = (long long)3 * S_ * L_;   // bcdt batch stride
    const long long sH    = (long long)DM * S_;       // h / hg / ho batch stride
    const long long sHZ   = (long long)2 * DM * S_;   // hz batch stride

    // 1) bcdt_raw[b] = w_bcdt @ x[b] + b_bcdt        (M=192, N=4096, K=512)
    gemm_nn_kernel<true><<<dim3(L_ / 64, 3 * S_ / 64, B_), blk>>>(
        w_bcdt, 0, x, sX, bcdt_raw, sBCDT, b_bcdt, L_, DM);

    // 2) depthwise 3x3 conv
    dwconv_kernel<<<dim3(3 * S_, B_), blk>>>(bcdt_raw, bcdt, w_dw, b_dw);

    // 3) AB = softmax_L(dt) * Bm  (in place over dt channels)
    softmax_ab_kernel<<<dim3(S_, B_), blk>>>(bcdt);

    // 4) h[b] = x[b] @ AB[b]^T                       (M=512, N=64, K=4096)
    gemm_nt_kernel<<<dim3(1, DM / 64, B_), blk>>>(
        x, sX, bcdt + (size_t)2 * S_ * L_, sBCDT, h, sH, S_, L_);

    // 5) hz[b] = w_hz @ h[b] + b_hz                  (M=1024, N=64, K=512)
    gemm_nn_kernel<true><<<dim3(1, 2 * DM / 64, B_), blk>>>(
        w_hz, 0, h, sH, hz, sHZ, b_hz, S_, DM);

    // 6) gating
    {
        const size_t total = (size_t)B_ * DM * S_;
        gate_kernel<<<(unsigned)((total + 255) / 256), blk>>>(hz, hg, Dskip);
    }

    // 7) ho[b] = w_out @ hg[b] + b_out               (M=512, N=64, K=512)
    gemm_nn_kernel<true><<<dim3(1, DM / 64, B_), blk>>>(
        w_out, 0, hg, sH, ho, sH, b_out, S_, DM);

    // 8) y[b] = ho[b] @ Cm[b]                        (M=512, N=4096, K=64)
    gemm_nn_kernel<false><<<dim3(L_ / 64, DM / 64, B_), blk>>>(
        ho, sH, bcdt + (size_t)S_ * L_, sBCDT, y, sX, nullptr, L_, S_);
}